// round 16
// baseline (speedup 1.0000x reference)
#include <cuda_runtime.h>
#include <cuda_bf16.h>
#include <math.h>

#define NN    50000
#define EE    800000
#define ET    (EE + NN)
#define F1    256
#define OUTC  128
#define NHEAD 4
#define NEG   0.2f

typedef unsigned uint32;

// ---------------- scratch (device globals) ---------------------------------
__device__ __align__(16) static float g_h2[(size_t)NN * OUTC];
__device__ __align__(16) static float g_as1[NN * NHEAD];
__device__ __align__(16) static float g_ad1[NN * NHEAD];
__device__ static float g_as2[NN], g_ad2[NN];
__device__ static float g_was1[128 * NHEAD], g_wad1[128 * NHEAD];
__device__ static float g_was2[256], g_wad2[256];
__device__ static int g_cnt[NN];            // zero at entry (static init / re-zeroed by csr_scan)
__device__ static int g_off[NN + 1];
__device__ static int g_ssrc[ET];
__device__ __align__(16) static __nv_bfloat16 g_axhi[(size_t)NN * NHEAD * 128];
__device__ __align__(16) static __nv_bfloat16 g_axlo[(size_t)NN * NHEAD * 128];
__device__ __align__(16) static __nv_bfloat16 g_o1hi[(size_t)NN * 256], g_o1lo[(size_t)NN * 256];
__device__ __align__(16) static __nv_bfloat16 g_w1hi[256 * 128], g_w1lo[256 * 128];
__device__ __align__(16) static __nv_bfloat16 g_w2hi[128 * 256], g_w2lo[128 * 256];

__device__ __forceinline__ void split2(float v, __nv_bfloat16& h, __nv_bfloat16& l) {
    h = __float2bfloat16(v);
    l = __float2bfloat16(v - __bfloat162float(h));
}

// ---------------- cp.async helpers -----------------------------------------
__device__ __forceinline__ uint32 smem_u32(const void* p) {
    return (uint32)__cvta_generic_to_shared(p);
}
__device__ __forceinline__ void cpa16(uint32 dst, const void* src, bool valid) {
    asm volatile("cp.async.cg.shared.global [%0], [%1], 16, %2;"
                 :: "r"(dst), "l"(src), "r"(valid ? 16 : 0));
}
#define CP_COMMIT() asm volatile("cp.async.commit_group;")
template <int N> __device__ __forceinline__ void cp_wait() {
    asm volatile("cp.async.wait_group %0;" :: "n"(N));
}

// ---------------- prologue (weight splits + folds + zeroing + CSR count) ---
// g_cnt is guaranteed zero on entry: zero-initialized at module load, and
// csr_scan re-zeros it after consuming, so every graph replay re-enters clean.
__global__ void prologue(const int* __restrict__ ei,
                         const float* __restrict__ W1,
                         const float* __restrict__ W2,
                         const float* __restrict__ av_s1,
                         const float* __restrict__ av_d1,
                         const float* __restrict__ av_s2,
                         const float* __restrict__ av_d2) {
    int i = blockIdx.x * blockDim.x + threadIdx.x;
    if (i < ET) {
        int dst = (i < EE) ? ei[EE + i] : (i - EE);
        atomicAdd(&g_cnt[dst], 1);
    }
    if (i < NN) { g_as2[i] = 0.f; g_ad2[i] = 0.f; }
    if (i < 128 * 256) {
        int k = i >> 8, p = i & 255;
        __nv_bfloat16 h, l;
        split2(W1[i], h, l);
        g_w1hi[p * 128 + k] = h; g_w1lo[p * 128 + k] = l;
    }
    if (i < 256 * 128) {
        int k = i >> 7, p = i & 127;
        __nv_bfloat16 h, l;
        split2(W2[i], h, l);
        g_w2hi[p * 256 + k] = h; g_w2lo[p * 256 + k] = l;
    }
    if (i < 128 * NHEAD) {
        int k = i >> 2, hd = i & 3;
        float s = 0.f, d = 0.f;
        const float* wr = W1 + k * 256 + hd * 64;
        const float* sv = av_s1 + hd * 64;
        const float* dv = av_d1 + hd * 64;
        for (int c = 0; c < 64; c++) { s += wr[c] * sv[c]; d += wr[c] * dv[c]; }
        g_was1[k * 4 + hd] = s; g_wad1[k * 4 + hd] = d;
    }
    if (i < 256) {
        float s = 0.f, d = 0.f;
        const float* wr = W2 + i * 128;
        for (int c = 0; c < 128; c++) { s += wr[c] * av_s2[c]; d += wr[c] * av_d2[c]; }
        g_was2[i] = s; g_wad2[i] = d;
    }
}

// ---------------- CSR scan (also re-zeros g_cnt for the next replay) -------
__global__ __launch_bounds__(1024) void csr_scan() {
    __shared__ int sp[1024];
    const int CH = (NN + 1023) / 1024;
    int t = threadIdx.x;
    int base = t * CH;
    int s = 0;
    for (int i = 0; i < CH; i++) { int j = base + i; if (j < NN) s += g_cnt[j]; }
    sp[t] = s;
    __syncthreads();
    for (int o = 1; o < 1024; o <<= 1) {
        int v = (t >= o) ? sp[t - o] : 0;
        __syncthreads();
        sp[t] += v;
        __syncthreads();
    }
    int p = sp[t] - s;
    for (int i = 0; i < CH; i++) {
        int j = base + i;
        if (j < NN) { g_off[j] = p; p += g_cnt[j]; g_cnt[j] = 0; }
    }
    if (t == 1023) g_off[NN] = sp[1023];
}

// destructive scatter: afterwards g_off[d] == old g_off[d+1]
// (agg kernels use start = d ? g_off[d-1] : 0, end = g_off[d])
__global__ void csr_scatter(const int* __restrict__ ei) {
    int e = blockIdx.x * blockDim.x + threadIdx.x;
    if (e >= ET) return;
    int src = (e < EE) ? ei[e]      : (e - EE);
    int dst = (e < EE) ? ei[EE + e] : (e - EE);
    int pos = atomicAdd(&g_off[dst], 1);
    g_ssrc[pos] = src;
}

// ---------------- layer-1 attention projections ----------------------------
__global__ __launch_bounds__(256) void alphas1_gemv(const float* __restrict__ x) {
    __shared__ float sw[8 * 128];
    int tid = threadIdx.x;
    for (int j = tid; j < 1024; j += 256) {
        int o = j >> 7, k = j & 127;
        sw[j] = (o < 4) ? g_was1[k * 4 + o] : g_wad1[k * 4 + (o - 4)];
    }
    __syncthreads();

    int warp = (blockIdx.x * 256 + tid) >> 5;
    int lane = tid & 31;
    if (warp >= NN) return;
    float4 xv = *(const float4*)(x + (size_t)warp * 128 + lane * 4);
    float p[8];
#pragma unroll
    for (int o = 0; o < 8; o++) {
        float4 wv = *(const float4*)&sw[o * 128 + lane * 4];
        p[o] = xv.x * wv.x + xv.y * wv.y + xv.z * wv.z + xv.w * wv.w;
    }
#pragma unroll
    for (int off = 16; off; off >>= 1)
#pragma unroll
        for (int o = 0; o < 8; o++)
            p[o] += __shfl_xor_sync(0xffffffffu, p[o], off);
    if (lane == 0) {
        *(float4*)(g_as1 + warp * 4) = make_float4(p[0], p[1], p[2], p[3]);
        *(float4*)(g_ad1 + warp * 4) = make_float4(p[4], p[5], p[6], p[7]);
    }
}

// ---------------- layer-1 aggregation of x (proven form) -------------------
__global__ __launch_bounds__(128) void agg1(const float* __restrict__ x) {
    constexpr int CAP = 512;
    const int dst = blockIdx.x;
    const int off = (dst == 0) ? 0 : g_off[dst - 1];
    const int deg = g_off[dst] - off;
    const int tid = threadIdx.x;
    const int lane = tid & 31;
    const int sub = tid >> 6;
    const int lt  = tid & 63;

    __shared__ int   s_src[CAP];
    __shared__ float s_alpha[CAP * NHEAD];
    __shared__ float s_den[NHEAD];
    __shared__ float s_part[64][8];

    if (tid < NHEAD) s_den[tid] = 0.f;

    float ax[NHEAD] = {0.f, 0.f, 0.f, 0.f};
    float ay[NHEAD] = {0.f, 0.f, 0.f, 0.f};

    for (int base = 0; base < deg; base += CAP) {
        const int cnt = min(CAP, deg - base);
        __syncthreads();

        {
            float4 ad = *(const float4*)(g_ad1 + dst * 4);
            float p0 = 0.f, p1 = 0.f, p2 = 0.f, p3 = 0.f;
            for (int i = tid; i < cnt; i += 128) {
                int src = g_ssrc[off + base + i];
                s_src[i] = src;
                float4 as = *(const float4*)(g_as1 + src * 4);
                float v0 = as.x + ad.x; v0 = (v0 > 0.f) ? v0 : NEG * v0;
                float v1 = as.y + ad.y; v1 = (v1 > 0.f) ? v1 : NEG * v1;
                float v2 = as.z + ad.z; v2 = (v2 > 0.f) ? v2 : NEG * v2;
                float v3 = as.w + ad.w; v3 = (v3 > 0.f) ? v3 : NEG * v3;
                float e0 = __expf(v0), e1 = __expf(v1);
                float e2 = __expf(v2), e3 = __expf(v3);
                *(float4*)&s_alpha[i * 4] = make_float4(e0, e1, e2, e3);
                p0 += e0; p1 += e1; p2 += e2; p3 += e3;
            }
#pragma unroll
            for (int o = 16; o; o >>= 1) {
                p0 += __shfl_xor_sync(0xffffffffu, p0, o);
                p1 += __shfl_xor_sync(0xffffffffu, p1, o);
                p2 += __shfl_xor_sync(0xffffffffu, p2, o);
                p3 += __shfl_xor_sync(0xffffffffu, p3, o);
            }
            if (lane == 0) {
                atomicAdd(&s_den[0], p0); atomicAdd(&s_den[1], p1);
                atomicAdd(&s_den[2], p2); atomicAdd(&s_den[3], p3);
            }
        }
        __syncthreads();

        int i = sub;
        for (; i + 2 < cnt; i += 4) {
            int sA = s_src[i], sB = s_src[i + 2];
            float4 alA = *(const float4*)&s_alpha[i * 4];
            float4 alB = *(const float4*)&s_alpha[(i + 2) * 4];
            float2 vA = *(const float2*)(x + (size_t)sA * 128 + 2 * lt);
            float2 vB = *(const float2*)(x + (size_t)sB * 128 + 2 * lt);
            ax[0] += alA.x * vA.x + alB.x * vB.x;
            ay[0] += alA.x * vA.y + alB.x * vB.y;
            ax[1] += alA.y * vA.x + alB.y * vB.x;
            ay[1] += alA.y * vA.y + alB.y * vB.y;
            ax[2] += alA.z * vA.x + alB.z * vB.x;
            ay[2] += alA.z * vA.y + alB.z * vB.y;
            ax[3] += alA.w * vA.x + alB.w * vB.x;
            ay[3] += alA.w * vA.y + alB.w * vB.y;
        }
        for (; i < cnt; i += 2) {
            int sA = s_src[i];
            float4 al = *(const float4*)&s_alpha[i * 4];
            float2 v = *(const float2*)(x + (size_t)sA * 128 + 2 * lt);
            ax[0] += al.x * v.x; ay[0] += al.x * v.y;
            ax[1] += al.y * v.x; ay[1] += al.y * v.y;
            ax[2] += al.z * v.x; ay[2] += al.z * v.y;
            ax[3] += al.w * v.x; ay[3] += al.w * v.y;
        }
    }
    __syncthreads();

    if (sub == 1) {
#pragma unroll
        for (int hd = 0; hd < NHEAD; hd++) {
            s_part[lt][hd * 2]     = ax[hd];
            s_part[lt][hd * 2 + 1] = ay[hd];
        }
    }
    __syncthreads();
    if (sub == 0) {
#pragma unroll
        for (int hd = 0; hd < NHEAD; hd++) {
            float inv = 1.f / s_den[hd];
            float r0 = (ax[hd] + s_part[lt][hd * 2])     * inv;
            float r1 = (ay[hd] + s_part[lt][hd * 2 + 1]) * inv;
            __nv_bfloat16 h0, l0, h1, l1;
            split2(r0, h0, l0); split2(r1, h1, l1);
            size_t p = ((size_t)dst * NHEAD + hd) * 128 + 2 * lt;
            __nv_bfloat162 hh; hh.x = h0; hh.y = h1;
            __nv_bfloat162 ll; ll.x = l0; ll.y = l1;
            *(__nv_bfloat162*)(g_axhi + p) = hh;
            *(__nv_bfloat162*)(g_axlo + p) = ll;
        }
    }
}

// ---------------- MMA helper -----------------------------------------------
__device__ __forceinline__ void mma16816(float* c, const uint32* a, uint32 b0, uint32 b1) {
    asm volatile(
        "mma.sync.aligned.m16n8k16.row.col.f32.bf16.bf16.f32 "
        "{%0,%1,%2,%3}, {%4,%5,%6,%7}, {%8,%9}, {%0,%1,%2,%3};"
        : "+f"(c[0]), "+f"(c[1]), "+f"(c[2]), "+f"(c[3])
        : "r"(a[0]), "r"(a[1]), "r"(a[2]), "r"(a[3]), "r"(b0), "r"(b1));
}

// layer-1 GEMM per head, cp.async 2-stage, fused as2/ad2 epilogue.
#define G0_ASTG 5120
#define G0_BSTG 2560
#define G0_SMEM ((4 * G0_ASTG + 4 * G0_BSTG) * 2)   // 61440 bytes

__global__ __launch_bounds__(256) void mma_gemm0(const float* __restrict__ b1) {
    extern __shared__ __nv_bfloat16 dyn[];
    __nv_bfloat16* sAh = dyn;
    __nv_bfloat16* sAl = dyn + 2 * G0_ASTG;
    __nv_bfloat16* sBh = dyn + 4 * G0_ASTG;
    __nv_bfloat16* sBl = dyn + 4 * G0_ASTG + 2 * G0_BSTG;

    const int hd = blockIdx.x;
    const int rowBase = blockIdx.y * 128;

    __shared__ float s_ws[64], s_wd[64];

    const int tid = threadIdx.x;
    const int wid = tid >> 5, lane = tid & 31;
    const int tig = lane & 3, grp = lane >> 2;
    const int mBase = wid * 16;

    const int lr = tid >> 1;
    const int lc = (tid & 1) * 16;

    if (tid < 64)       s_ws[tid] = g_was2[hd * 64 + tid];
    else if (tid < 128) s_wd[tid - 64] = g_wad2[hd * 64 + tid - 64];

    float acc[8][4];
#pragma unroll
    for (int a = 0; a < 8; a++)
#pragma unroll
        for (int b = 0; b < 4; b++) acc[a][b] = 0.f;

    const int dstA = rowBase + lr;
    const bool av = dstA < NN;
    const size_t aRow = ((size_t)dstA * NHEAD + hd) * 128;

    // B chunk decomposition: 512 16B chunks per stage (hi 0-255, lo 256-511), 2/thread
    const int bc0 = tid, bc1 = tid + 256;

    auto load_stage = [&](int st, int k0) {
        uint32 dAh = smem_u32(sAh + st * G0_ASTG + lr * 40 + lc);
        uint32 dAl = smem_u32(sAl + st * G0_ASTG + lr * 40 + lc);
        const __nv_bfloat16* sh = g_axhi + aRow + k0 + lc;
        const __nv_bfloat16* sl = g_axlo + aRow + k0 + lc;
        cpa16(dAh, sh, av);      cpa16(dAh + 16, sh + 8, av);
        cpa16(dAl, sl, av);      cpa16(dAl + 16, sl + 8, av);
#pragma unroll
        for (int q = 0; q < 2; q++) {
            int c = (q == 0) ? bc0 : bc1;
            int isLo = c >> 8;
            int cc = c & 255;
            int row = cc >> 2;           // 0..63
            int seg = (cc & 3) * 8;      // 0,8,16,24 bf16
            const __nv_bfloat16* srcB =
                (isLo ? g_w1lo : g_w1hi) + (size_t)(hd * 64 + row) * 128 + k0 + seg;
            __nv_bfloat16* dstB =
                (isLo ? sBl : sBh) + st * G0_BSTG + row * 40 + seg;
            cpa16(smem_u32(dstB), srcB, true);
        }
    };

    load_stage(0, 0);
    CP_COMMIT();

    constexpr int S = 4;
#pragma unroll
    for (int s = 0; s < S; s++) {
        if (s + 1 < S) { load_stage((s + 1) & 1, (s + 1) * 32); CP_COMMIT(); }
        if (s + 1 < S) cp_wait<1>(); else cp_wait<0>();
        __syncthreads();

        const int st = s & 1;
        const __nv_bfloat16* pAh = sAh + st * G0_ASTG;
        const __nv_bfloat16* pAl = sAl + st * G0_ASTG;
        const __nv_bfloat16* pBh = sBh + st * G0_BSTG;
        const __nv_bfloat16* pBl = sBl + st * G0_BSTG;

#pragma unroll
        for (int ks = 0; ks < 32; ks += 16) {
            uint32 fah[4], fal[4];
            int r0 = mBase + grp;
            fah[0] = *(const uint32*)&pAh[(r0    ) * 40 + ks + 2 * tig];
            fah[1] = *(const uint32*)&pAh[(r0 + 8) * 40 + ks + 2 * tig];
            fah[2] = *(const uint32*)&pAh[(r0    ) * 40 + ks + 2 * tig + 8];
            fah[3] = *(const uint32*)&pAh[(r0 + 8) * 40 + ks + 2 * tig + 8];
            fal[0] = *(const uint32*)&pAl[(r0    ) * 40 + ks + 2 * tig];
            fal[1] = *(const uint32*)&pAl[(r0 + 8) * 40 + ks + 2 * tig];
            fal[2] = *(const uint32*)&pAl[(r0    ) * 40 + ks + 2 * tig + 8];
            fal[3] = *(const uint32*)&pAl[(r0 + 8) * 40 + ks + 2 * tig + 8];
#pragma unroll
            for (int nf = 0; nf < 8; nf++) {
                int c0 = nf * 8 + grp;
                uint32 bh0r = *(const uint32*)&pBh[c0 * 40 + ks + 2 * tig];
                uint32 bh1r = *(const uint32*)&pBh[c0 * 40 + ks + 2 * tig + 8];
                uint32 bl0r = *(const uint32*)&pBl[c0 * 40 + ks + 2 * tig];
                uint32 bl1r = *(const uint32*)&pBl[c0 * 40 + ks + 2 * tig + 8];
                mma16816(acc[nf], fah, bh0r, bh1r);
                mma16816(acc[nf], fah, bl0r, bl1r);
                mma16816(acc[nf], fal, bh0r, bh1r);
            }
        }
        __syncthreads();
    }

    float ps[2] = {0.f, 0.f}, pd_[2] = {0.f, 0.f};
#pragma unroll
    for (int nf = 0; nf < 8; nf++) {
        int cc = nf * 8 + 2 * tig;
        int col = hd * 64 + cc;
#pragma unroll
        for (int half = 0; half < 2; half++) {
            int r = rowBase + mBase + grp + half * 8;
            if (r < NN) {
                float v0 = acc[nf][half * 2 + 0] + b1[col];
                float v1 = acc[nf][half * 2 + 1] + b1[col + 1];
                v0 = (v0 > 0.f) ? v0 : expm1f(v0);
                v1 = (v1 > 0.f) ? v1 : expm1f(v1);
                __nv_bfloat16 h0, l0, h1, l1;
                split2(v0, h0, l0); split2(v1, h1, l1);
                size_t p = (size_t)r * 256 + col;
                g_o1hi[p] = h0; g_o1hi[p + 1] = h1;
                g_o1lo[p] = l0; g_o1lo[p + 1] = l1;
                ps[half]  += v0 * s_ws[cc] + v1 * s_ws[cc + 1];
                pd_[half] += v0 * s_wd[cc] + v1 * s_wd[cc + 1];
            }
        }
    }
#pragma unroll
    for (int half = 0; half < 2; half++) {
        ps[half]  += __shfl_xor_sync(0xffffffffu, ps[half], 1);
        ps[half]  += __shfl_xor_sync(0xffffffffu, ps[half], 2);
        pd_[half] += __shfl_xor_sync(0xffffffffu, pd_[half], 1);
        pd_[half] += __shfl_xor_sync(0xffffffffu, pd_[half], 2);
        if (tig == 0) {
            int r = rowBase + mBase + grp + half * 8;
            if (r < NN) {
                atomicAdd(&g_as2[r], ps[half]);
                atomicAdd(&g_ad2[r], pd_[half]);
            }
        }
    }
}

// layer-2 GEMM: cp.async 2-stage.
#define G1_STG 5120
#define G1_SMEM (8 * G1_STG * 2)   // 81920 bytes

__global__ __launch_bounds__(256) void mma_gemm1() {
    extern __shared__ __nv_bfloat16 dyn[];
    __nv_bfloat16* sAh = dyn;
    __nv_bfloat16* sAl = dyn + 2 * G1_STG;
    __nv_bfloat16* sBh = dyn + 4 * G1_STG;
    __nv_bfloat16* sBl = dyn + 6 * G1_STG;

    constexpr int K = 256;
    constexpr int P = 128;

    const int tid = threadIdx.x;
    const int wid = tid >> 5, lane = tid & 31;
    const int tig = lane & 3, grp = lane >> 2;
    const int mBase = (wid & 1) * 64, nBase = (wid >> 1) * 32;
    const int rowBase = blockIdx.y * 128;

    const int lr = tid >> 1;
    const int lc = (tid & 1) * 16;

    float acc[4][4][4];
#pragma unroll
    for (int a = 0; a < 4; a++)
#pragma unroll
        for (int b = 0; b < 4; b++)
#pragma unroll
            for (int c = 0; c < 4; c++) acc[a][b][c] = 0.f;

    const int ar = rowBase + lr;
    const bool av = ar < NN;
    const int br = lr;

    auto load_stage = [&](int st, int k0) {
        uint32 dAh = smem_u32(sAh + st * G1_STG + lr * 40 + lc);
        uint32 dAl = smem_u32(sAl + st * G1_STG + lr * 40 + lc);
        const __nv_bfloat16* sh = g_o1hi + (size_t)ar * K + k0 + lc;
        const __nv_bfloat16* sl = g_o1lo + (size_t)ar * K + k0 + lc;
        cpa16(dAh, sh, av);      cpa16(dAh + 16, sh + 8, av);
        cpa16(dAl, sl, av);      cpa16(dAl + 16, sl + 8, av);
        uint32 dBh = smem_u32(sBh + st * G1_STG + lr * 40 + lc);
        uint32 dBl = smem_u32(sBl + st * G1_STG + lr * 40 + lc);
        const __nv_bfloat16* bh = g_w2hi + (size_t)br * K + k0 + lc;
        const __nv_bfloat16* bl = g_w2lo + (size_t)br * K + k0 + lc;
        cpa16(dBh, bh, true);    cpa16(dBh + 16, bh + 8, true);
        cpa16(dBl, bl, true);    cpa16(dBl + 16, bl + 8, true);
    };

    load_stage(0, 0);
    CP_COMMIT();

    constexpr int S = 8;
#pragma unroll
    for (int s = 0; s < S; s++) {
        if (s + 1 < S) { load_stage((s + 1) & 1, (s + 1) * 32); CP_COMMIT(); }
        if (s + 1 < S) cp_wait<1>(); else cp_wait<0>();
        __syncthreads();

        const int st = s & 1;
        const __nv_bfloat16* pAh = sAh + st * G1_STG;
        const __nv_bfloat16* pAl = sAl + st * G1_STG;
        const __nv_bfloat16* pBh = sBh + st * G1_STG;
        const __nv_bfloat16* pBl = sBl + st * G1_STG;

#pragma unroll
        for (int ks = 0; ks < 32; ks += 16) {
            uint32 fah[4][4], fal[4][4];
#pragma unroll
            for (int mf = 0; mf < 4; mf++) {
                int r0 = mBase + mf * 16 + grp;
                fah[mf][0] = *(const uint32*)&pAh[(r0    ) * 40 + ks + 2 * tig];
                fah[mf][1] = *(const uint32*)&pAh[(r0 + 8) * 40 + ks + 2 * tig];
                fah[mf][2] = *(const uint32*)&pAh[(r0    ) * 40 + ks + 2 * tig + 8];
                fah[mf][3] = *(const uint32*)&pAh[(r0 + 8) * 40 + ks + 2 * tig + 8];
                fal[mf][0] = *(const uint32*)&pAl[(r0    ) * 40 + ks + 2 * tig];
                fal[mf][1] = *(const uint32*)&pAl[(r0 + 8) * 40 + ks + 2 * tig];
                fal[mf][2] = *(const uint32*)&pAl[(r0    ) * 40 + ks + 2 * tig + 8];
                fal[mf][3] = *(const uint32*)&pAl[(r0 + 8) * 40 + ks + 2 * tig + 8];
            }
#pragma unroll
            for (int nf = 0; nf < 4; nf++) {
                int c0 = nBase + nf * 8 + grp;
                uint32 bh0r = *(const uint32*)&pBh[c0 * 40 + ks + 2 * tig];
                uint32 bh1r = *(const uint32*)&pBh[c0 * 40 + ks + 2 * tig + 8];
                uint32 bl0r = *(const uint32*)&pBl[c0 * 40 + ks + 2 * tig];
                uint32 bl1r = *(const uint32*)&pBl[c0 * 40 + ks + 2 * tig + 8];
#pragma unroll
                for (int mf = 0; mf < 4; mf++) {
                    mma16816(acc[mf][nf], fah[mf], bh0r, bh1r);
                    mma16816(acc[mf][nf], fah[mf], bl0r, bl1r);
                    mma16816(acc[mf][nf], fal[mf], bh0r, bh1r);
                }
            }
        }
        __syncthreads();
    }

#pragma unroll
    for (int mf = 0; mf < 4; mf++)
#pragma unroll
        for (int nf = 0; nf < 4; nf++) {
            int r = rowBase + mBase + mf * 16 + grp;
            int c = nBase + nf * 8 + 2 * tig;
            if (r < NN)
                *(float2*)(g_h2 + (size_t)r * P + c) = make_float2(acc[mf][nf][0], acc[mf][nf][1]);
            if (r + 8 < NN)
                *(float2*)(g_h2 + (size_t)(r + 8) * P + c) = make_float2(acc[mf][nf][2], acc[mf][nf][3]);
        }
}

// ---------------- layer-2 fused softmax + aggregate ------------------------
__global__ __launch_bounds__(128) void agg2(const float* __restrict__ bias,
                                            float* __restrict__ outp) {
    constexpr int CAP = 512;
    const int dst = blockIdx.x;
    const int off = (dst == 0) ? 0 : g_off[dst - 1];
    const int deg = g_off[dst] - off;
    const int tid = threadIdx.x;
    const int lane = tid & 31;
    const int sub = tid >> 6;
    const int lt  = tid & 63;

    __shared__ int   s_src[CAP];
    __shared__ float s_alpha[CAP];
    __shared__ float s_den1[1];
    __shared__ float s_part[64][2];

    if (tid == 0) s_den1[0] = 0.f;

    float ax = 0.f, ay = 0.f;

    for (int base = 0; base < deg; base += CAP) {
        const int cnt = min(CAP, deg - base);
        __syncthreads();

        float adv = g_ad2[dst];
        float p = 0.f;
        for (int i = tid; i < cnt; i += 128) {
            int src = g_ssrc[off + base + i];
            s_src[i] = src;
            float v = g_as2[src] + adv;
            v = (v > 0.f) ? v : NEG * v;
            float ex = __expf(v);
            s_alpha[i] = ex;
            p += ex;
        }
#pragma unroll
        for (int o = 16; o; o >>= 1)
            p += __shfl_xor_sync(0xffffffffu, p, o);
        if (lane == 0) atomicAdd(&s_den1[0], p);
        __syncthreads();

        int i = sub;
        for (; i + 2 < cnt; i += 4) {
            int sA = s_src[i], sB = s_src[i + 2];
            float aA = s_alpha[i], aB = s_alpha[i + 2];
            float2 vA = *(const float2*)(g_h2 + (size_t)sA * OUTC + 2 * lt);
            float2 vB = *(const float2*)(g_h2 + (size_t)sB * OUTC + 2 * lt);
            ax += aA * vA.x + aB * vB.x;
            ay += aA * vA.y + aB * vB.y;
        }
        for (; i < cnt; i += 2) {
            int sA = s_src[i];
            float aA = s_alpha[i];
            float2 v = *(const float2*)(g_h2 + (size_t)sA * OUTC + 2 * lt);
            ax += aA * v.x;
            ay += aA * v.y;
        }
    }
    __syncthreads();

    if (sub == 1) { s_part[lt][0] = ax; s_part[lt][1] = ay; }
    __syncthreads();
    if (sub == 0) {
        float inv = 1.f / s_den1[0];
        float r0 = (ax + s_part[lt][0]) * inv + bias[2 * lt];
        float r1 = (ay + s_part[lt][1]) * inv + bias[2 * lt + 1];
        *(float2*)(outp + (size_t)dst * OUTC + 2 * lt) = make_float2(r0, r1);
    }
}

// ---------------- launch ---------------------------------------------------
extern "C" void kernel_launch(void* const* d_in, const int* in_sizes, int n_in,
                              void* d_out, int out_size) {
    const float* x   = (const float*)d_in[0];
    const int*   ei  = (const int*)d_in[1];
    const float* W1  = (const float*)d_in[2];
    const float* as1 = (const float*)d_in[3];
    const float* ad1 = (const float*)d_in[4];
    const float* b1  = (const float*)d_in[5];
    const float* W2  = (const float*)d_in[6];
    const float* as2 = (const float*)d_in[7];
    const float* ad2 = (const float*)d_in[8];
    const float* b2  = (const float*)d_in[9];
    float*       out = (float*)d_out;

    const int T = 256;

    static bool attr_done = false;
    if (!attr_done) {
        cudaFuncSetAttribute(mma_gemm0, cudaFuncAttributeMaxDynamicSharedMemorySize, G0_SMEM);
        cudaFuncSetAttribute(mma_gemm1, cudaFuncAttributeMaxDynamicSharedMemorySize, G1_SMEM);
        attr_done = true;
    }

    prologue<<<(ET + T - 1) / T, T>>>(ei, W1, W2, as1, ad1, as2, ad2);
    csr_scan<<<1, 1024>>>();
    csr_scatter<<<(ET + T - 1) / T, T>>>(ei);

    // ---- layer 1 ----
    alphas1_gemv<<<(NN * 32 + T - 1) / T, T>>>(x);
    agg1<<<NN, 128>>>(x);
    mma_gemm0<<<dim3(NHEAD, (NN + 127) / 128), T, G0_SMEM>>>(b1);

    // ---- layer 2 ----
    mma_gemm1<<<dim3(1, (NN + 127) / 128), T, G1_SMEM>>>();
    agg2<<<NN, 128>>>(b2, out);
}

// round 17
// speedup vs baseline: 1.0776x; 1.0776x over previous
#include <cuda_runtime.h>
#include <cuda_bf16.h>
#include <math.h>

#define NN    50000
#define EE    800000
#define ET    (EE + NN)
#define F1    256
#define OUTC  128
#define NHEAD 4
#define NEG   0.2f

typedef unsigned uint32;

// ---------------- scratch (device globals) ---------------------------------
__device__ __align__(16) static float g_h2[(size_t)NN * OUTC];
__device__ __align__(16) static float g_as1[NN * NHEAD];
__device__ __align__(16) static float g_ad1[NN * NHEAD];
__device__ static float g_as2[NN], g_ad2[NN];
__device__ static float g_was1[128 * NHEAD], g_wad1[128 * NHEAD];
__device__ static float g_was2[256], g_wad2[256];
__device__ static int g_cnt[NN];
__device__ static int g_off[NN + 1];
__device__ static int g_ssrc[ET];
__device__ __align__(16) static __nv_bfloat16 g_axhi[(size_t)NN * NHEAD * 128];
__device__ __align__(16) static __nv_bfloat16 g_axlo[(size_t)NN * NHEAD * 128];
__device__ __align__(16) static __nv_bfloat16 g_o1hi[(size_t)NN * 256], g_o1lo[(size_t)NN * 256];
__device__ __align__(16) static __nv_bfloat16 g_w1hi[256 * 128], g_w1lo[256 * 128];
__device__ __align__(16) static __nv_bfloat16 g_w2hi[128 * 256], g_w2lo[128 * 256];

__device__ __forceinline__ void split2(float v, __nv_bfloat16& h, __nv_bfloat16& l) {
    h = __float2bfloat16(v);
    l = __float2bfloat16(v - __bfloat162float(h));
}

// ---------------- cp.async helpers -----------------------------------------
__device__ __forceinline__ uint32 smem_u32(const void* p) {
    return (uint32)__cvta_generic_to_shared(p);
}
__device__ __forceinline__ void cpa16(uint32 dst, const void* src, bool valid) {
    asm volatile("cp.async.cg.shared.global [%0], [%1], 16, %2;"
                 :: "r"(dst), "l"(src), "r"(valid ? 16 : 0));
}
#define CP_COMMIT() asm volatile("cp.async.commit_group;")
template <int N> __device__ __forceinline__ void cp_wait() {
    asm volatile("cp.async.wait_group %0;" :: "n"(N));
}

// ---------------- prologue -------------------------------------------------
__global__ void prologue(const float* __restrict__ W1,
                         const float* __restrict__ W2,
                         const float* __restrict__ av_s1,
                         const float* __restrict__ av_d1,
                         const float* __restrict__ av_s2,
                         const float* __restrict__ av_d2) {
    int i = blockIdx.x * blockDim.x + threadIdx.x;
    if (i < NN) { g_cnt[i] = 0; g_as2[i] = 0.f; g_ad2[i] = 0.f; }
    if (i < 128 * 256) {
        int k = i >> 8, p = i & 255;
        __nv_bfloat16 h, l;
        split2(W1[i], h, l);
        g_w1hi[p * 128 + k] = h; g_w1lo[p * 128 + k] = l;
    }
    if (i < 256 * 128) {
        int k = i >> 7, p = i & 127;
        __nv_bfloat16 h, l;
        split2(W2[i], h, l);
        g_w2hi[p * 256 + k] = h; g_w2lo[p * 256 + k] = l;
    }
    if (i < 128 * NHEAD) {
        int k = i >> 2, hd = i & 3;
        float s = 0.f, d = 0.f;
        const float* wr = W1 + k * 256 + hd * 64;
        const float* sv = av_s1 + hd * 64;
        const float* dv = av_d1 + hd * 64;
        for (int c = 0; c < 64; c++) { s += wr[c] * sv[c]; d += wr[c] * dv[c]; }
        g_was1[k * 4 + hd] = s; g_wad1[k * 4 + hd] = d;
    }
    if (i < 256) {
        float s = 0.f, d = 0.f;
        const float* wr = W2 + i * 128;
        for (int c = 0; c < 128; c++) { s += wr[c] * av_s2[c]; d += wr[c] * av_d2[c]; }
        g_was2[i] = s; g_wad2[i] = d;
    }
}

// ---------------- CSR build ------------------------------------------------
__global__ void csr_count(const int* __restrict__ ei) {
    int e = blockIdx.x * blockDim.x + threadIdx.x;
    if (e >= ET) return;
    int dst = (e < EE) ? ei[EE + e] : (e - EE);
    atomicAdd(&g_cnt[dst], 1);
}

__global__ __launch_bounds__(1024) void csr_scan() {
    __shared__ int sp[1024];
    const int CH = (NN + 1023) / 1024;
    int t = threadIdx.x;
    int base = t * CH;
    int s = 0;
    for (int i = 0; i < CH; i++) { int j = base + i; if (j < NN) s += g_cnt[j]; }
    sp[t] = s;
    __syncthreads();
    for (int o = 1; o < 1024; o <<= 1) {
        int v = (t >= o) ? sp[t - o] : 0;
        __syncthreads();
        sp[t] += v;
        __syncthreads();
    }
    int p = sp[t] - s;
    for (int i = 0; i < CH; i++) {
        int j = base + i;
        if (j < NN) { g_off[j] = p; p += g_cnt[j]; }
    }
    if (t == 1023) g_off[NN] = sp[1023];
}

// destructive scatter: afterwards g_off[d] == old g_off[d+1]
__global__ void csr_scatter(const int* __restrict__ ei) {
    int e = blockIdx.x * blockDim.x + threadIdx.x;
    if (e >= ET) return;
    int src = (e < EE) ? ei[e]      : (e - EE);
    int dst = (e < EE) ? ei[EE + e] : (e - EE);
    int pos = atomicAdd(&g_off[dst], 1);
    g_ssrc[pos] = src;
}

// ---------------- layer-1 attention projections ----------------------------
__global__ __launch_bounds__(256) void alphas1_gemv(const float* __restrict__ x) {
    __shared__ float sw[8 * 128];
    int tid = threadIdx.x;
    for (int j = tid; j < 1024; j += 256) {
        int o = j >> 7, k = j & 127;
        sw[j] = (o < 4) ? g_was1[k * 4 + o] : g_wad1[k * 4 + (o - 4)];
    }
    __syncthreads();

    int warp = (blockIdx.x * 256 + tid) >> 5;
    int lane = tid & 31;
    if (warp >= NN) return;
    float4 xv = *(const float4*)(x + (size_t)warp * 128 + lane * 4);
    float p[8];
#pragma unroll
    for (int o = 0; o < 8; o++) {
        float4 wv = *(const float4*)&sw[o * 128 + lane * 4];
        p[o] = xv.x * wv.x + xv.y * wv.y + xv.z * wv.z + xv.w * wv.w;
    }
#pragma unroll
    for (int off = 16; off; off >>= 1)
#pragma unroll
        for (int o = 0; o < 8; o++)
            p[o] += __shfl_xor_sync(0xffffffffu, p[o], off);
    if (lane == 0) {
        *(float4*)(g_as1 + warp * 4) = make_float4(p[0], p[1], p[2], p[3]);
        *(float4*)(g_ad1 + warp * 4) = make_float4(p[4], p[5], p[6], p[7]);
    }
}

// ---------------- layer-1 aggregation of x (proven form) -------------------
__global__ __launch_bounds__(128) void agg1(const float* __restrict__ x) {
    constexpr int CAP = 512;
    const int dst = blockIdx.x;
    const int off = (dst == 0) ? 0 : g_off[dst - 1];
    const int deg = g_off[dst] - off;
    const int tid = threadIdx.x;
    const int lane = tid & 31;
    const int sub = tid >> 6;
    const int lt  = tid & 63;

    __shared__ int   s_src[CAP];
    __shared__ float s_alpha[CAP * NHEAD];
    __shared__ float s_den[NHEAD];
    __shared__ float s_part[64][8];

    if (tid < NHEAD) s_den[tid] = 0.f;

    float ax[NHEAD] = {0.f, 0.f, 0.f, 0.f};
    float ay[NHEAD] = {0.f, 0.f, 0.f, 0.f};

    for (int base = 0; base < deg; base += CAP) {
        const int cnt = min(CAP, deg - base);
        __syncthreads();

        {
            float4 ad = *(const float4*)(g_ad1 + dst * 4);
            float p0 = 0.f, p1 = 0.f, p2 = 0.f, p3 = 0.f;
            for (int i = tid; i < cnt; i += 128) {
                int src = g_ssrc[off + base + i];
                s_src[i] = src;
                float4 as = *(const float4*)(g_as1 + src * 4);
                float v0 = as.x + ad.x; v0 = (v0 > 0.f) ? v0 : NEG * v0;
                float v1 = as.y + ad.y; v1 = (v1 > 0.f) ? v1 : NEG * v1;
                float v2 = as.z + ad.z; v2 = (v2 > 0.f) ? v2 : NEG * v2;
                float v3 = as.w + ad.w; v3 = (v3 > 0.f) ? v3 : NEG * v3;
                float e0 = __expf(v0), e1 = __expf(v1);
                float e2 = __expf(v2), e3 = __expf(v3);
                *(float4*)&s_alpha[i * 4] = make_float4(e0, e1, e2, e3);
                p0 += e0; p1 += e1; p2 += e2; p3 += e3;
            }
#pragma unroll
            for (int o = 16; o; o >>= 1) {
                p0 += __shfl_xor_sync(0xffffffffu, p0, o);
                p1 += __shfl_xor_sync(0xffffffffu, p1, o);
                p2 += __shfl_xor_sync(0xffffffffu, p2, o);
                p3 += __shfl_xor_sync(0xffffffffu, p3, o);
            }
            if (lane == 0) {
                atomicAdd(&s_den[0], p0); atomicAdd(&s_den[1], p1);
                atomicAdd(&s_den[2], p2); atomicAdd(&s_den[3], p3);
            }
        }
        __syncthreads();

        int i = sub;
        for (; i + 2 < cnt; i += 4) {
            int sA = s_src[i], sB = s_src[i + 2];
            float4 alA = *(const float4*)&s_alpha[i * 4];
            float4 alB = *(const float4*)&s_alpha[(i + 2) * 4];
            float2 vA = *(const float2*)(x + (size_t)sA * 128 + 2 * lt);
            float2 vB = *(const float2*)(x + (size_t)sB * 128 + 2 * lt);
            ax[0] += alA.x * vA.x + alB.x * vB.x;
            ay[0] += alA.x * vA.y + alB.x * vB.y;
            ax[1] += alA.y * vA.x + alB.y * vB.x;
            ay[1] += alA.y * vA.y + alB.y * vB.y;
            ax[2] += alA.z * vA.x + alB.z * vB.x;
            ay[2] += alA.z * vA.y + alB.z * vB.y;
            ax[3] += alA.w * vA.x + alB.w * vB.x;
            ay[3] += alA.w * vA.y + alB.w * vB.y;
        }
        for (; i < cnt; i += 2) {
            int sA = s_src[i];
            float4 al = *(const float4*)&s_alpha[i * 4];
            float2 v = *(const float2*)(x + (size_t)sA * 128 + 2 * lt);
            ax[0] += al.x * v.x; ay[0] += al.x * v.y;
            ax[1] += al.y * v.x; ay[1] += al.y * v.y;
            ax[2] += al.z * v.x; ay[2] += al.z * v.y;
            ax[3] += al.w * v.x; ay[3] += al.w * v.y;
        }
    }
    __syncthreads();

    if (sub == 1) {
#pragma unroll
        for (int hd = 0; hd < NHEAD; hd++) {
            s_part[lt][hd * 2]     = ax[hd];
            s_part[lt][hd * 2 + 1] = ay[hd];
        }
    }
    __syncthreads();
    if (sub == 0) {
#pragma unroll
        for (int hd = 0; hd < NHEAD; hd++) {
            float inv = 1.f / s_den[hd];
            float r0 = (ax[hd] + s_part[lt][hd * 2])     * inv;
            float r1 = (ay[hd] + s_part[lt][hd * 2 + 1]) * inv;
            __nv_bfloat16 h0, l0, h1, l1;
            split2(r0, h0, l0); split2(r1, h1, l1);
            size_t p = ((size_t)dst * NHEAD + hd) * 128 + 2 * lt;
            __nv_bfloat162 hh; hh.x = h0; hh.y = h1;
            __nv_bfloat162 ll; ll.x = l0; ll.y = l1;
            *(__nv_bfloat162*)(g_axhi + p) = hh;
            *(__nv_bfloat162*)(g_axlo + p) = ll;
        }
    }
}

// ---------------- MMA helper -----------------------------------------------
__device__ __forceinline__ void mma16816(float* c, const uint32* a, uint32 b0, uint32 b1) {
    asm volatile(
        "mma.sync.aligned.m16n8k16.row.col.f32.bf16.bf16.f32 "
        "{%0,%1,%2,%3}, {%4,%5,%6,%7}, {%8,%9}, {%0,%1,%2,%3};"
        : "+f"(c[0]), "+f"(c[1]), "+f"(c[2]), "+f"(c[3])
        : "r"(a[0]), "r"(a[1]), "r"(a[2]), "r"(a[3]), "r"(b0), "r"(b1));
}

// layer-1 GEMM per head, cp.async 2-stage, fused as2/ad2 epilogue.
#define G0_ASTG 5120
#define G0_BSTG 2560
#define G0_SMEM ((4 * G0_ASTG + 4 * G0_BSTG) * 2)   // 61440 bytes

__global__ __launch_bounds__(256) void mma_gemm0(const float* __restrict__ b1) {
    extern __shared__ __nv_bfloat16 dyn[];
    __nv_bfloat16* sAh = dyn;
    __nv_bfloat16* sAl = dyn + 2 * G0_ASTG;
    __nv_bfloat16* sBh = dyn + 4 * G0_ASTG;
    __nv_bfloat16* sBl = dyn + 4 * G0_ASTG + 2 * G0_BSTG;

    const int hd = blockIdx.x;
    const int rowBase = blockIdx.y * 128;

    __shared__ float s_ws[64], s_wd[64];

    const int tid = threadIdx.x;
    const int wid = tid >> 5, lane = tid & 31;
    const int tig = lane & 3, grp = lane >> 2;
    const int mBase = wid * 16;

    const int lr = tid >> 1;
    const int lc = (tid & 1) * 16;

    if (tid < 64)       s_ws[tid] = g_was2[hd * 64 + tid];
    else if (tid < 128) s_wd[tid - 64] = g_wad2[hd * 64 + tid - 64];

    float acc[8][4];
#pragma unroll
    for (int a = 0; a < 8; a++)
#pragma unroll
        for (int b = 0; b < 4; b++) acc[a][b] = 0.f;

    const int dstA = rowBase + lr;
    const bool av = dstA < NN;
    const size_t aRow = ((size_t)dstA * NHEAD + hd) * 128;
    const size_t bRow = (size_t)(hd * 64 + ((tid >> 1) & 63)) * 128;
    const int r2 = tid >> 1;

    auto load_stage = [&](int st, int k0) {
        uint32 dAh = smem_u32(sAh + st * G0_ASTG + lr * 40 + lc);
        uint32 dAl = smem_u32(sAl + st * G0_ASTG + lr * 40 + lc);
        const __nv_bfloat16* sh = g_axhi + aRow + k0 + lc;
        const __nv_bfloat16* sl = g_axlo + aRow + k0 + lc;
        cpa16(dAh, sh, av);      cpa16(dAh + 16, sh + 8, av);
        cpa16(dAl, sl, av);      cpa16(dAl + 16, sl + 8, av);
        if (tid < 128) {
            uint32 dBh = smem_u32(sBh + st * G0_BSTG + r2 * 40 + lc);
            uint32 dBl = smem_u32(sBl + st * G0_BSTG + r2 * 40 + lc);
            const __nv_bfloat16* bh = g_w1hi + bRow + k0 + lc;
            const __nv_bfloat16* bl = g_w1lo + bRow + k0 + lc;
            cpa16(dBh, bh, true);    cpa16(dBh + 16, bh + 8, true);
            cpa16(dBl, bl, true);    cpa16(dBl + 16, bl + 8, true);
        }
    };

    load_stage(0, 0);
    CP_COMMIT();

    constexpr int S = 4;
#pragma unroll
    for (int s = 0; s < S; s++) {
        if (s + 1 < S) { load_stage((s + 1) & 1, (s + 1) * 32); CP_COMMIT(); }
        if (s + 1 < S) cp_wait<1>(); else cp_wait<0>();
        __syncthreads();

        const int st = s & 1;
        const __nv_bfloat16* pAh = sAh + st * G0_ASTG;
        const __nv_bfloat16* pAl = sAl + st * G0_ASTG;
        const __nv_bfloat16* pBh = sBh + st * G0_BSTG;
        const __nv_bfloat16* pBl = sBl + st * G0_BSTG;

#pragma unroll
        for (int ks = 0; ks < 32; ks += 16) {
            uint32 fah[4], fal[4];
            int r0 = mBase + grp;
            fah[0] = *(const uint32*)&pAh[(r0    ) * 40 + ks + 2 * tig];
            fah[1] = *(const uint32*)&pAh[(r0 + 8) * 40 + ks + 2 * tig];
            fah[2] = *(const uint32*)&pAh[(r0    ) * 40 + ks + 2 * tig + 8];
            fah[3] = *(const uint32*)&pAh[(r0 + 8) * 40 + ks + 2 * tig + 8];
            fal[0] = *(const uint32*)&pAl[(r0    ) * 40 + ks + 2 * tig];
            fal[1] = *(const uint32*)&pAl[(r0 + 8) * 40 + ks + 2 * tig];
            fal[2] = *(const uint32*)&pAl[(r0    ) * 40 + ks + 2 * tig + 8];
            fal[3] = *(const uint32*)&pAl[(r0 + 8) * 40 + ks + 2 * tig + 8];
#pragma unroll
            for (int nf = 0; nf < 8; nf++) {
                int c0 = nf * 8 + grp;
                uint32 bh0r = *(const uint32*)&pBh[c0 * 40 + ks + 2 * tig];
                uint32 bh1r = *(const uint32*)&pBh[c0 * 40 + ks + 2 * tig + 8];
                uint32 bl0r = *(const uint32*)&pBl[c0 * 40 + ks + 2 * tig];
                uint32 bl1r = *(const uint32*)&pBl[c0 * 40 + ks + 2 * tig + 8];
                mma16816(acc[nf], fah, bh0r, bh1r);
                mma16816(acc[nf], fah, bl0r, bl1r);
                mma16816(acc[nf], fal, bh0r, bh1r);
            }
        }
        __syncthreads();
    }

    float ps[2] = {0.f, 0.f}, pd_[2] = {0.f, 0.f};
#pragma unroll
    for (int nf = 0; nf < 8; nf++) {
        int cc = nf * 8 + 2 * tig;
        int col = hd * 64 + cc;
#pragma unroll
        for (int half = 0; half < 2; half++) {
            int r = rowBase + mBase + grp + half * 8;
            if (r < NN) {
                float v0 = acc[nf][half * 2 + 0] + b1[col];
                float v1 = acc[nf][half * 2 + 1] + b1[col + 1];
                v0 = (v0 > 0.f) ? v0 : expm1f(v0);
                v1 = (v1 > 0.f) ? v1 : expm1f(v1);
                __nv_bfloat16 h0, l0, h1, l1;
                split2(v0, h0, l0); split2(v1, h1, l1);
                size_t p = (size_t)r * 256 + col;
                g_o1hi[p] = h0; g_o1hi[p + 1] = h1;
                g_o1lo[p] = l0; g_o1lo[p + 1] = l1;
                ps[half]  += v0 * s_ws[cc] + v1 * s_ws[cc + 1];
                pd_[half] += v0 * s_wd[cc] + v1 * s_wd[cc + 1];
            }
        }
    }
#pragma unroll
    for (int half = 0; half < 2; half++) {
        ps[half]  += __shfl_xor_sync(0xffffffffu, ps[half], 1);
        ps[half]  += __shfl_xor_sync(0xffffffffu, ps[half], 2);
        pd_[half] += __shfl_xor_sync(0xffffffffu, pd_[half], 1);
        pd_[half] += __shfl_xor_sync(0xffffffffu, pd_[half], 2);
        if (tig == 0) {
            int r = rowBase + mBase + grp + half * 8;
            if (r < NN) {
                atomicAdd(&g_as2[r], ps[half]);
                atomicAdd(&g_ad2[r], pd_[half]);
            }
        }
    }
}

// layer-2 GEMM: cp.async 2-stage.
#define G1_STG 5120
#define G1_SMEM (8 * G1_STG * 2)   // 81920 bytes

__global__ __launch_bounds__(256) void mma_gemm1() {
    extern __shared__ __nv_bfloat16 dyn[];
    __nv_bfloat16* sAh = dyn;
    __nv_bfloat16* sAl = dyn + 2 * G1_STG;
    __nv_bfloat16* sBh = dyn + 4 * G1_STG;
    __nv_bfloat16* sBl = dyn + 6 * G1_STG;

    constexpr int K = 256;
    constexpr int P = 128;

    const int tid = threadIdx.x;
    const int wid = tid >> 5, lane = tid & 31;
    const int tig = lane & 3, grp = lane >> 2;
    const int mBase = (wid & 1) * 64, nBase = (wid >> 1) * 32;
    const int rowBase = blockIdx.y * 128;

    const int lr = tid >> 1;
    const int lc = (tid & 1) * 16;

    float acc[4][4][4];
#pragma unroll
    for (int a = 0; a < 4; a++)
#pragma unroll
        for (int b = 0; b < 4; b++)
#pragma unroll
            for (int c = 0; c < 4; c++) acc[a][b][c] = 0.f;

    const int ar = rowBase + lr;
    const bool av = ar < NN;
    const int br = lr;

    auto load_stage = [&](int st, int k0) {
        uint32 dAh = smem_u32(sAh + st * G1_STG + lr * 40 + lc);
        uint32 dAl = smem_u32(sAl + st * G1_STG + lr * 40 + lc);
        const __nv_bfloat16* sh = g_o1hi + (size_t)ar * K + k0 + lc;
        const __nv_bfloat16* sl = g_o1lo + (size_t)ar * K + k0 + lc;
        cpa16(dAh, sh, av);      cpa16(dAh + 16, sh + 8, av);
        cpa16(dAl, sl, av);      cpa16(dAl + 16, sl + 8, av);
        uint32 dBh = smem_u32(sBh + st * G1_STG + lr * 40 + lc);
        uint32 dBl = smem_u32(sBl + st * G1_STG + lr * 40 + lc);
        const __nv_bfloat16* bh = g_w2hi + (size_t)br * K + k0 + lc;
        const __nv_bfloat16* bl = g_w2lo + (size_t)br * K + k0 + lc;
        cpa16(dBh, bh, true);    cpa16(dBh + 16, bh + 8, true);
        cpa16(dBl, bl, true);    cpa16(dBl + 16, bl + 8, true);
    };

    load_stage(0, 0);
    CP_COMMIT();

    constexpr int S = 8;
#pragma unroll
    for (int s = 0; s < S; s++) {
        if (s + 1 < S) { load_stage((s + 1) & 1, (s + 1) * 32); CP_COMMIT(); }
        if (s + 1 < S) cp_wait<1>(); else cp_wait<0>();
        __syncthreads();

        const int st = s & 1;
        const __nv_bfloat16* pAh = sAh + st * G1_STG;
        const __nv_bfloat16* pAl = sAl + st * G1_STG;
        const __nv_bfloat16* pBh = sBh + st * G1_STG;
        const __nv_bfloat16* pBl = sBl + st * G1_STG;

#pragma unroll
        for (int ks = 0; ks < 32; ks += 16) {
            uint32 fah[4][4], fal[4][4];
#pragma unroll
            for (int mf = 0; mf < 4; mf++) {
                int r0 = mBase + mf * 16 + grp;
                fah[mf][0] = *(const uint32*)&pAh[(r0    ) * 40 + ks + 2 * tig];
                fah[mf][1] = *(const uint32*)&pAh[(r0 + 8) * 40 + ks + 2 * tig];
                fah[mf][2] = *(const uint32*)&pAh[(r0    ) * 40 + ks + 2 * tig + 8];
                fah[mf][3] = *(const uint32*)&pAh[(r0 + 8) * 40 + ks + 2 * tig + 8];
                fal[mf][0] = *(const uint32*)&pAl[(r0    ) * 40 + ks + 2 * tig];
                fal[mf][1] = *(const uint32*)&pAl[(r0 + 8) * 40 + ks + 2 * tig];
                fal[mf][2] = *(const uint32*)&pAl[(r0    ) * 40 + ks + 2 * tig + 8];
                fal[mf][3] = *(const uint32*)&pAl[(r0 + 8) * 40 + ks + 2 * tig + 8];
            }
#pragma unroll
            for (int nf = 0; nf < 4; nf++) {
                int c0 = nBase + nf * 8 + grp;
                uint32 bh0r = *(const uint32*)&pBh[c0 * 40 + ks + 2 * tig];
                uint32 bh1r = *(const uint32*)&pBh[c0 * 40 + ks + 2 * tig + 8];
                uint32 bl0r = *(const uint32*)&pBl[c0 * 40 + ks + 2 * tig];
                uint32 bl1r = *(const uint32*)&pBl[c0 * 40 + ks + 2 * tig + 8];
#pragma unroll
                for (int mf = 0; mf < 4; mf++) {
                    mma16816(acc[mf][nf], fah[mf], bh0r, bh1r);
                    mma16816(acc[mf][nf], fah[mf], bl0r, bl1r);
                    mma16816(acc[mf][nf], fal[mf], bh0r, bh1r);
                }
            }
        }
        __syncthreads();
    }

#pragma unroll
    for (int mf = 0; mf < 4; mf++)
#pragma unroll
        for (int nf = 0; nf < 4; nf++) {
            int r = rowBase + mBase + mf * 16 + grp;
            int c = nBase + nf * 8 + 2 * tig;
            if (r < NN)
                *(float2*)(g_h2 + (size_t)r * P + c) = make_float2(acc[mf][nf][0], acc[mf][nf][1]);
            if (r + 8 < NN)
                *(float2*)(g_h2 + (size_t)(r + 8) * P + c) = make_float2(acc[mf][nf][2], acc[mf][nf][3]);
        }
}

// ---------------- layer-2 fused softmax + aggregate ------------------------
__global__ __launch_bounds__(128) void agg2(const float* __restrict__ bias,
                                            float* __restrict__ outp) {
    constexpr int CAP = 512;
    const int dst = blockIdx.x;
    const int off = (dst == 0) ? 0 : g_off[dst - 1];
    const int deg = g_off[dst] - off;
    const int tid = threadIdx.x;
    const int lane = tid & 31;
    const int sub = tid >> 6;
    const int lt  = tid & 63;

    __shared__ int   s_src[CAP];
    __shared__ float s_alpha[CAP];
    __shared__ float s_den1[1];
    __shared__ float s_part[64][2];

    if (tid == 0) s_den1[0] = 0.f;

    float ax = 0.f, ay = 0.f;

    for (int base = 0; base < deg; base += CAP) {
        const int cnt = min(CAP, deg - base);
        __syncthreads();

        float adv = g_ad2[dst];
        float p = 0.f;
        for (int i = tid; i < cnt; i += 128) {
            int src = g_ssrc[off + base + i];
            s_src[i] = src;
            float v = g_as2[src] + adv;
            v = (v > 0.f) ? v : NEG * v;
            float ex = __expf(v);
            s_alpha[i] = ex;
            p += ex;
        }
#pragma unroll
        for (int o = 16; o; o >>= 1)
            p += __shfl_xor_sync(0xffffffffu, p, o);
        if (lane == 0) atomicAdd(&s_den1[0], p);
        __syncthreads();

        int i = sub;
        for (; i + 2 < cnt; i += 4) {
            int sA = s_src[i], sB = s_src[i + 2];
            float aA = s_alpha[i], aB = s_alpha[i + 2];
            float2 vA = *(const float2*)(g_h2 + (size_t)sA * OUTC + 2 * lt);
            float2 vB = *(const float2*)(g_h2 + (size_t)sB * OUTC + 2 * lt);
            ax += aA * vA.x + aB * vB.x;
            ay += aA * vA.y + aB * vB.y;
        }
        for (; i < cnt; i += 2) {
            int sA = s_src[i];
            float aA = s_alpha[i];
            float2 v = *(const float2*)(g_h2 + (size_t)sA * OUTC + 2 * lt);
            ax += aA * v.x;
            ay += aA * v.y;
        }
    }
    __syncthreads();

    if (sub == 1) { s_part[lt][0] = ax; s_part[lt][1] = ay; }
    __syncthreads();
    if (sub == 0) {
        float inv = 1.f / s_den1[0];
        float r0 = (ax + s_part[lt][0]) * inv + bias[2 * lt];
        float r1 = (ay + s_part[lt][1]) * inv + bias[2 * lt + 1];
        *(float2*)(outp + (size_t)dst * OUTC + 2 * lt) = make_float2(r0, r1);
    }
}

// ---------------- launch ---------------------------------------------------
extern "C" void kernel_launch(void* const* d_in, const int* in_sizes, int n_in,
                              void* d_out, int out_size) {
    const float* x   = (const float*)d_in[0];
    const int*   ei  = (const int*)d_in[1];
    const float* W1  = (const float*)d_in[2];
    const float* as1 = (const float*)d_in[3];
    const float* ad1 = (const float*)d_in[4];
    const float* b1  = (const float*)d_in[5];
    const float* W2  = (const float*)d_in[6];
    const float* as2 = (const float*)d_in[7];
    const float* ad2 = (const float*)d_in[8];
    const float* b2  = (const float*)d_in[9];
    float*       out = (float*)d_out;

    const int T = 256;

    // One-time setup (first call = uncaptured correctness run)
    static cudaStream_t s_side = nullptr;
    static cudaEvent_t ev_fork = nullptr, ev_join = nullptr;
    static bool attr_done = false;
    if (!attr_done) {
        cudaFuncSetAttribute(mma_gemm0, cudaFuncAttributeMaxDynamicSharedMemorySize, G0_SMEM);
        cudaFuncSetAttribute(mma_gemm1, cudaFuncAttributeMaxDynamicSharedMemorySize, G1_SMEM);
        cudaStreamCreateWithFlags(&s_side, cudaStreamNonBlocking);
        cudaEventCreateWithFlags(&ev_fork, cudaEventDisableTiming);
        cudaEventCreateWithFlags(&ev_join, cudaEventDisableTiming);
        attr_done = true;
    }

    prologue<<<(NN + T - 1) / T, T>>>(W1, W2, as1, ad1, as2, ad2);

    // fork: alphas1_gemv (side stream) runs concurrently with CSR build (main)
    cudaEventRecord(ev_fork, 0);
    cudaStreamWaitEvent(s_side, ev_fork, 0);
    alphas1_gemv<<<(NN * 32 + T - 1) / T, T, 0, s_side>>>(x);
    cudaEventRecord(ev_join, s_side);

    csr_count<<<(ET + T - 1) / T, T>>>(ei);
    csr_scan<<<1, 1024>>>();
    csr_scatter<<<(ET + T - 1) / T, T>>>(ei);

    // join before agg1 (needs both CSR and alphas)
    cudaStreamWaitEvent(0, ev_join, 0);

    // ---- layer 1 ----
    agg1<<<NN, 128>>>(x);
    mma_gemm0<<<dim3(NHEAD, (NN + 127) / 128), T, G0_SMEM>>>(b1);

    // ---- layer 2 ----
    mma_gemm1<<<dim3(1, (NN + 127) / 128), T, G1_SMEM>>>();
    agg2<<<NN, 128>>>(b2, out);
}